// round 4
// baseline (speedup 1.0000x reference)
#include <cuda_runtime.h>
#include <cuda_fp16.h>
#include <cstdint>
#include <cstddef>

// ===================== problem constants =====================
#define SEQLEN 256
#define NBATCH 256
// hidden = 1024, gates = 4096, concat K = 2048

// ===================== device scratch ========================
static __device__ __half g_Wcat[(size_t)4096 * 2048];     // [Wcomb | Whh], rows n'=4u+g
static __device__ __half g_WfcT16[(size_t)1024 * 1024];   // W_fc^T fp16 (prep GEMM B)
static __device__ __half g_Wfc16[(size_t)1024 * 1024];    // W_fc fp16 (final GEMM B)
static __device__ float  g_bias0[4096];                   // perm(b_ih+b_hh)
static __device__ float  g_biasA[4096];                   // bias0 + perm(W_ih@b_fc)
static __device__ __half g_X16[2][(size_t)NBATCH * 2048]; // per row: [c16 | h16]
static __device__ float  g_c32[2][(size_t)NBATCH * 1024]; // fp32 cell state

// ===================== helpers ===============================
__device__ __forceinline__ uint32_t smem_u32_of(const void* p) {
    uint32_t a;
    asm("{ .reg .u64 t; cvta.to.shared.u64 t, %1; cvt.u32.u64 %0, t; }" : "=r"(a) : "l"(p));
    return a;
}
__device__ __forceinline__ uint32_t f22u(float a, float b) {
    __half2 h = __floats2half2_rn(a, b);
    return *reinterpret_cast<uint32_t*>(&h);
}
__device__ __forceinline__ float sigf(float x) { return 1.f / (1.f + __expf(-x)); }

__device__ __forceinline__ void ldsm4(uint32_t* r, uint32_t addr) {
    asm volatile("ldmatrix.sync.aligned.m8n8.x4.shared.b16 {%0,%1,%2,%3}, [%4];"
                 : "=r"(r[0]), "=r"(r[1]), "=r"(r[2]), "=r"(r[3]) : "r"(addr));
}
__device__ __forceinline__ void mma16816(float* d, const uint32_t* a, const uint32_t* b) {
    asm volatile("mma.sync.aligned.m16n8k16.row.col.f32.f16.f16.f32 "
                 "{%0,%1,%2,%3}, {%4,%5,%6,%7}, {%8,%9}, {%0,%1,%2,%3};"
                 : "+f"(d[0]), "+f"(d[1]), "+f"(d[2]), "+f"(d[3])
                 : "r"(a[0]), "r"(a[1]), "r"(a[2]), "r"(a[3]), "r"(b[0]), "r"(b[1]));
}
__device__ __forceinline__ void cp16(uint32_t saddr, const void* g) {
    asm volatile("cp.async.cg.shared.global [%0], [%1], 16;" :: "r"(saddr), "l"(g));
}
__device__ __forceinline__ void cp_commit() { asm volatile("cp.async.commit_group;" ::: "memory"); }
template <int N> __device__ __forceinline__ void cp_wait() {
    asm volatile("cp.async.wait_group %0;" :: "n"(N) : "memory");
}
#define SWZ(off) ((off) ^ (((off) >> 3) & 0x70))

// ===================== GEMM core =============================
// acc[2][4][4] (fp32) = A[128, K] @ B[64, K]^T on a 128x64 CTA tile.
// 8 warps as 4(M) x 2(N), warp tile 32x32, mma.sync m16n8k16.
// K consumed in 64-wide chunks, double-buffered smem (A 16KB + B 8KB per buf).
// A32: A is fp32 (converted on load, plain ld/st); else fp16 via cp.async.
template <bool A32>
__device__ __forceinline__ void gemm_core(
    const void* Aptr_, int lda, const __half* Bptr, int ldb,
    int kChunks, char* smem, float acc[2][4][4])
{
    const int tid = threadIdx.x;
    const int lane = tid & 31, wid = tid >> 5;
    const int wm = wid & 3, wn = wid >> 2;
    const uint32_t base = smem_u32_of(smem);

    #pragma unroll
    for (int mi = 0; mi < 2; ++mi)
        #pragma unroll
        for (int nf = 0; nf < 4; ++nf)
            #pragma unroll
            for (int e = 0; e < 4; ++e) acc[mi][nf][e] = 0.f;

    auto load_chunk = [&](int c, int buf) {
        const int k0 = c * 64;
        char* dA = smem + buf * 24576;
        char* dB = dA + 16384;
        if (A32) {
            const float* Af = (const float*)Aptr_;
            #pragma unroll
            for (int rnd = 0; rnd < 4; ++rnd) {
                int idx = rnd * 256 + tid;
                int row = idx >> 3, kb = idx & 7;
                const float* g = Af + (size_t)row * lda + k0 + kb * 8;
                float4 f0 = *(const float4*)g;
                float4 f1 = *(const float4*)(g + 4);
                uint4 v = make_uint4(f22u(f0.x, f0.y), f22u(f0.z, f0.w),
                                     f22u(f1.x, f1.y), f22u(f1.z, f1.w));
                uint32_t off = (uint32_t)(row * 128 + kb * 16);
                *(uint4*)(dA + SWZ(off)) = v;
            }
            #pragma unroll
            for (int rnd = 0; rnd < 2; ++rnd) {
                int idx = rnd * 256 + tid;
                int n = idx >> 3, kb = idx & 7;
                uint4 v = *(const uint4*)(Bptr + (size_t)n * ldb + k0 + kb * 8);
                uint32_t off = (uint32_t)(n * 128 + kb * 16);
                *(uint4*)(dB + SWZ(off)) = v;
            }
        } else {
            const __half* Ah = (const __half*)Aptr_;
            uint32_t sA = base + buf * 24576;
            uint32_t sB = sA + 16384;
            #pragma unroll
            for (int rnd = 0; rnd < 4; ++rnd) {
                int idx = rnd * 256 + tid;
                int row = idx >> 3, kb = idx & 7;
                uint32_t off = (uint32_t)(row * 128 + kb * 16);
                cp16(sA + SWZ(off), Ah + (size_t)row * lda + k0 + kb * 8);
            }
            #pragma unroll
            for (int rnd = 0; rnd < 2; ++rnd) {
                int idx = rnd * 256 + tid;
                int n = idx >> 3, kb = idx & 7;
                uint32_t off = (uint32_t)(n * 128 + kb * 16);
                cp16(sB + SWZ(off), Bptr + (size_t)n * ldb + k0 + kb * 8);
            }
            cp_commit();
        }
    };

    load_chunk(0, 0);

    for (int c = 0; c < kChunks; ++c) {
        const int buf = c & 1;
        const bool more = (c + 1 < kChunks);
        if (more) load_chunk(c + 1, buf ^ 1);
        if (!A32) { if (more) cp_wait<1>(); else cp_wait<0>(); }
        __syncthreads();

        const uint32_t Ab = base + buf * 24576;
        const uint32_t Bb = Ab + 16384;
        #pragma unroll
        for (int kk = 0; kk < 4; ++kk) {
            uint32_t ra[2][4], rb[2][4];
            #pragma unroll
            for (int mi = 0; mi < 2; ++mi) {
                int m = wm * 32 + mi * 16 + (lane & 7) + ((lane >> 3) & 1) * 8;
                int kbyte = kk * 32 + ((lane >> 4) & 1) * 16;
                uint32_t off = (uint32_t)(m * 128 + kbyte);
                ldsm4(ra[mi], Ab + SWZ(off));
            }
            #pragma unroll
            for (int p = 0; p < 2; ++p) {
                int n = wn * 32 + p * 16 + (lane & 7) + ((lane >> 4) & 1) * 8;
                int kbyte = kk * 32 + ((lane >> 3) & 1) * 16;
                uint32_t off = (uint32_t)(n * 128 + kbyte);
                ldsm4(rb[p], Bb + SWZ(off));
            }
            #pragma unroll
            for (int mi = 0; mi < 2; ++mi)
                #pragma unroll
                for (int nf = 0; nf < 4; ++nf)
                    mma16816(acc[mi][nf], ra[mi], rb[nf >> 1] + (nf & 1) * 2);
        }
        __syncthreads();
    }
}

// scatter accum into gstage[128][65] (padded fp32 staging in smem)
__device__ __forceinline__ void store_acc(float* gstage, float acc[2][4][4], int tid) {
    const int lane = tid & 31, wid = tid >> 5;
    const int wm = wid & 3, wn = wid >> 2;
    #pragma unroll
    for (int mi = 0; mi < 2; ++mi)
        #pragma unroll
        for (int nf = 0; nf < 4; ++nf) {
            int m = wm * 32 + mi * 16 + (lane >> 2);
            int n = wn * 32 + nf * 8 + 2 * (lane & 3);
            gstage[m * 65 + n]           = acc[mi][nf][0];
            gstage[m * 65 + n + 1]       = acc[mi][nf][1];
            gstage[(m + 8) * 65 + n]     = acc[mi][nf][2];
            gstage[(m + 8) * 65 + n + 1] = acc[mi][nf][3];
        }
}

// ===================== prep kernels ==========================
__global__ void k_convert_wfc(const float* __restrict__ Wfc) {
    int i = blockIdx.x * 256 + threadIdx.x;          // 1M elems
    int n = i >> 10, k = i & 1023;
    g_WfcT16[i] = __float2half(Wfc[(size_t)k * 1024 + n]);
    g_Wfc16[i]  = __float2half(Wfc[i]);
}

__global__ void k_convert_whh(const float* __restrict__ Whh) {
    int i = blockIdx.x * 256 + threadIdx.x;          // 4M elems
    int np = i >> 10, j = i & 1023;
    int r = (np & 3) * 1024 + (np >> 2);             // orig gate row
    g_Wcat[(size_t)np * 2048 + 1024 + j] = __float2half(Whh[(size_t)r * 1024 + j]);
}

__global__ void k_bias(const float* __restrict__ Wih, const float* __restrict__ bih,
                       const float* __restrict__ bhh, const float* __restrict__ bfc) {
    int w = (blockIdx.x * blockDim.x + threadIdx.x) >> 5;   // n' row, 0..4095
    int lane = threadIdx.x & 31;
    if (w >= 4096) return;
    int r = (w & 3) * 1024 + (w >> 2);
    float s = 0.f;
    for (int j = lane; j < 1024; j += 32) s += Wih[(size_t)r * 1024 + j] * bfc[j];
    #pragma unroll
    for (int o = 16; o; o >>= 1) s += __shfl_down_sync(0xffffffffu, s, o);
    if (lane == 0) {
        float b0 = bih[r] + bhh[r];
        g_bias0[w] = b0;
        g_biasA[w] = b0 + s;
    }
}

__global__ void k_init(const float* __restrict__ cvec) {
    int i = blockIdx.x * 256 + threadIdx.x;          // 256K elems
    int b = i >> 10, u = i & 1023;
    float cv = cvec[i];
    g_c32[0][i] = cv;
    g_X16[0][(size_t)b * 2048 + u] = __float2half(0.f);          // i_0 = 0 fold
    g_X16[0][(size_t)b * 2048 + 1024 + u] = __float2half(cv);    // h_0 = c_vector
}

// Wcomb = W_ih @ W_fc, fp16 into g_Wcat left half with row perm n'=4u+g.
// grid (32, 16): mt = 128-row tile of W_ih, nt = 64-col tile.
__global__ __launch_bounds__(256, 1) void k_prep(const float* __restrict__ Wih) {
    extern __shared__ char smem[];
    const int mt = blockIdx.x, nt = blockIdx.y;
    float acc[2][4][4];
    gemm_core<true>(Wih + (size_t)mt * 128 * 1024, 1024,
                    g_WfcT16 + (size_t)nt * 64 * 1024, 1024, 16, smem, acc);
    float* gstage = (float*)smem;
    store_acc(gstage, acc, threadIdx.x);
    __syncthreads();
    #pragma unroll
    for (int i = 0; i < 32; ++i) {                   // 8192 elems
        int idx = i * 256 + threadIdx.x;
        int rl = idx >> 6, col = idx & 63;
        int r = mt * 128 + rl;
        int np = 4 * (r & 1023) + (r >> 10);
        g_Wcat[(size_t)np * 2048 + nt * 64 + col] = __float2half(gstage[rl * 65 + col]);
    }
}

// ===================== step kernel ===========================
// grid (2, 64): mt batch tile, nt = 16-unit tile (64 gate cols).
__global__ __launch_bounds__(256, 1) void k_step(int sb, int useA, int t,
                                                 float* __restrict__ hout,
                                                 float* __restrict__ cout) {
    extern __shared__ char smem[];
    const int tid = threadIdx.x;
    const int mt = blockIdx.x, nt = blockIdx.y;

    const __half* Xsrc = g_X16[sb];
    __half* Xdst = g_X16[sb ^ 1];
    const float* csrc = g_c32[sb];
    float* cdst = g_c32[sb ^ 1];
    const float* bias = useA ? g_biasA : g_bias0;

    float acc[2][4][4];
    gemm_core<false>(Xsrc + (size_t)mt * 128 * 2048, 2048,
                     g_Wcat + (size_t)nt * 64 * 2048, 2048, 32, smem, acc);
    float* gstage = (float*)smem;
    store_acc(gstage, acc, tid);
    __syncthreads();

    #pragma unroll
    for (int i = 0; i < 8; ++i) {                    // 2048 cells
        int idx = i * 256 + tid;
        int row = idx >> 4, ul = idx & 15;
        int ug = nt * 16 + ul;
        int bg = mt * 128 + row;
        float ip = gstage[row * 65 + 4 * ul + 0] + bias[4 * ug + 0];
        float fp = gstage[row * 65 + 4 * ul + 1] + bias[4 * ug + 1];
        float gp = gstage[row * 65 + 4 * ul + 2] + bias[4 * ug + 2];
        float op = gstage[row * 65 + 4 * ul + 3] + bias[4 * ug + 3];
        float cprev = csrc[(size_t)bg * 1024 + ug];
        float cn = sigf(fp) * cprev + sigf(ip) * tanhf(gp);
        float hn = sigf(op) * tanhf(cn);
        cdst[(size_t)bg * 1024 + ug] = cn;
        Xdst[(size_t)bg * 2048 + ug] = __float2half(cn);
        Xdst[(size_t)bg * 2048 + 1024 + ug] = __float2half(hn);
        size_t o = (size_t)bg * (SEQLEN * 1024) + (size_t)t * 1024 + ug;
        hout[o] = hn;
        cout[o] = cn;
    }
}

// ===================== final outputs GEMM ====================
// outputs[m, n] = c_states[m, :] @ W_fc[n, :] + b_fc[n]; M=65536, N=1024, K=1024.
// grid (16, 512): nt fast-varying for A-tile L2 reuse.
__global__ __launch_bounds__(256, 1) void k_final(const float* __restrict__ Call,
                                                  const float* __restrict__ bfc,
                                                  float* __restrict__ outp) {
    extern __shared__ char smem[];
    const int nt = blockIdx.x, mt = blockIdx.y;
    float acc[2][4][4];
    gemm_core<true>(Call + (size_t)mt * 128 * 1024, 1024,
                    g_Wfc16 + (size_t)nt * 64 * 1024, 1024, 16, smem, acc);
    float* gstage = (float*)smem;
    store_acc(gstage, acc, threadIdx.x);
    __syncthreads();
    #pragma unroll
    for (int i = 0; i < 32; ++i) {
        int idx = i * 256 + threadIdx.x;
        int rl = idx >> 6, col = idx & 63;
        outp[(size_t)(mt * 128 + rl) * 1024 + nt * 64 + col] =
            gstage[rl * 65 + col] + bfc[nt * 64 + col];
    }
}

// ===================== host launcher =========================
extern "C" void kernel_launch(void* const* d_in, const int* in_sizes, int n_in,
                              void* d_out, int out_size) {
    const float* c_vec = (const float*)d_in[0];
    const float* W_ih  = (const float*)d_in[1];
    const float* W_hh  = (const float*)d_in[2];
    const float* b_ih  = (const float*)d_in[3];
    const float* b_hh  = (const float*)d_in[4];
    const float* W_fc  = (const float*)d_in[5];
    const float* b_fc  = (const float*)d_in[6];
    float* out = (float*)d_out;
    const size_t HSZ = (size_t)NBATCH * SEQLEN * 1024;
    float* hout = out;
    float* cout = out + HSZ;
    float* oout = out + 2 * HSZ;

    const int SM = 49152;
    cudaFuncSetAttribute(k_prep,  cudaFuncAttributeMaxDynamicSharedMemorySize, SM);
    cudaFuncSetAttribute(k_step,  cudaFuncAttributeMaxDynamicSharedMemorySize, SM);
    cudaFuncSetAttribute(k_final, cudaFuncAttributeMaxDynamicSharedMemorySize, SM);

    k_convert_wfc<<<4096, 256>>>(W_fc);
    k_convert_whh<<<16384, 256>>>(W_hh);
    k_bias<<<512, 256>>>(W_ih, b_ih, b_hh, b_fc);
    k_init<<<1024, 256>>>(c_vec);

    dim3 gp(32, 16);
    k_prep<<<gp, 256, SM>>>(W_ih);

    dim3 gs(2, 64);
    for (int t = 0; t < SEQLEN; ++t)
        k_step<<<gs, 256, SM>>>(t & 1, (t > 0) ? 1 : 0, t, hout, cout);

    dim3 gf(16, 512);
    k_final<<<gf, 256, SM>>>(cout, b_fc, oout);
}

// round 8
// speedup vs baseline: 1.1011x; 1.1011x over previous
#include <cuda_runtime.h>
#include <cuda_fp16.h>
#include <cstdint>
#include <cstddef>

// ===================== problem constants =====================
#define SEQLEN 256
#define NBATCH 256
// hidden = 1024, gates = 4096, concat K = 2048

// ===================== device scratch ========================
static __device__ __half g_Wcat[(size_t)4096 * 2048];     // [Wcomb | Whh], rows n'=4u+g
static __device__ __half g_WfcT16[(size_t)1024 * 1024];   // W_fc^T fp16 (prep GEMM B)
static __device__ __half g_Wfc16[(size_t)1024 * 1024];    // W_fc fp16 (final GEMM B)
static __device__ float  g_bias0[4096];                   // perm(b_ih+b_hh)
static __device__ float  g_biasA[4096];                   // bias0 + perm(W_ih@b_fc)
static __device__ __half g_X16[2][(size_t)NBATCH * 2048]; // per row: [c16 | h16]
static __device__ unsigned g_bar;                         // grid barrier counter

// ===================== helpers ===============================
__device__ __forceinline__ uint32_t smem_u32_of(const void* p) {
    uint32_t a;
    asm("{ .reg .u64 t; cvta.to.shared.u64 t, %1; cvt.u32.u64 %0, t; }" : "=r"(a) : "l"(p));
    return a;
}
__device__ __forceinline__ uint32_t f22u(float a, float b) {
    __half2 h = __floats2half2_rn(a, b);
    return *reinterpret_cast<uint32_t*>(&h);
}
__device__ __forceinline__ float sigf(float x) { return 1.f / (1.f + __expf(-x)); }

__device__ __forceinline__ void ldsm4(uint32_t* r, uint32_t addr) {
    asm volatile("ldmatrix.sync.aligned.m8n8.x4.shared.b16 {%0,%1,%2,%3}, [%4];"
                 : "=r"(r[0]), "=r"(r[1]), "=r"(r[2]), "=r"(r[3]) : "r"(addr));
}
__device__ __forceinline__ void mma16816(float* d, const uint32_t* a, const uint32_t* b) {
    asm volatile("mma.sync.aligned.m16n8k16.row.col.f32.f16.f16.f32 "
                 "{%0,%1,%2,%3}, {%4,%5,%6,%7}, {%8,%9}, {%0,%1,%2,%3};"
                 : "+f"(d[0]), "+f"(d[1]), "+f"(d[2]), "+f"(d[3])
                 : "r"(a[0]), "r"(a[1]), "r"(a[2]), "r"(a[3]), "r"(b[0]), "r"(b[1]));
}
__device__ __forceinline__ void cp16(uint32_t saddr, const void* g) {
    asm volatile("cp.async.cg.shared.global [%0], [%1], 16;" :: "r"(saddr), "l"(g));
}
__device__ __forceinline__ void cp_commit() { asm volatile("cp.async.commit_group;" ::: "memory"); }
template <int N> __device__ __forceinline__ void cp_wait() {
    asm volatile("cp.async.wait_group %0;" :: "n"(N) : "memory");
}
#define SWZ(off) ((off) ^ (((off) >> 3) & 0x70))

// ===================== GEMM core (launch-per-tile path) ======
// acc[2][4][4] (fp32) = A[128, K] @ B[64, K]^T on a 128x64 CTA tile.
// 8 warps as 4(M) x 2(N), warp tile 32x32, mma.sync m16n8k16.
// K consumed in 64-wide chunks, double-buffered smem (A 16KB + B 8KB per buf).
template <bool A32>
__device__ __forceinline__ void gemm_core(
    const void* Aptr_, int lda, const __half* Bptr, int ldb,
    int kChunks, char* smem, float acc[2][4][4])
{
    const int tid = threadIdx.x;
    const int lane = tid & 31, wid = tid >> 5;
    const int wm = wid & 3, wn = wid >> 2;
    const uint32_t base = smem_u32_of(smem);

    #pragma unroll
    for (int mi = 0; mi < 2; ++mi)
        #pragma unroll
        for (int nf = 0; nf < 4; ++nf)
            #pragma unroll
            for (int e = 0; e < 4; ++e) acc[mi][nf][e] = 0.f;

    auto load_chunk = [&](int c, int buf) {
        const int k0 = c * 64;
        char* dA = smem + buf * 24576;
        char* dB = dA + 16384;
        if (A32) {
            const float* Af = (const float*)Aptr_;
            #pragma unroll
            for (int rnd = 0; rnd < 4; ++rnd) {
                int idx = rnd * 256 + tid;
                int row = idx >> 3, kb = idx & 7;
                const float* g = Af + (size_t)row * lda + k0 + kb * 8;
                float4 f0 = *(const float4*)g;
                float4 f1 = *(const float4*)(g + 4);
                uint4 v = make_uint4(f22u(f0.x, f0.y), f22u(f0.z, f0.w),
                                     f22u(f1.x, f1.y), f22u(f1.z, f1.w));
                uint32_t off = (uint32_t)(row * 128 + kb * 16);
                *(uint4*)(dA + SWZ(off)) = v;
            }
            #pragma unroll
            for (int rnd = 0; rnd < 2; ++rnd) {
                int idx = rnd * 256 + tid;
                int n = idx >> 3, kb = idx & 7;
                uint4 v = *(const uint4*)(Bptr + (size_t)n * ldb + k0 + kb * 8);
                uint32_t off = (uint32_t)(n * 128 + kb * 16);
                *(uint4*)(dB + SWZ(off)) = v;
            }
        } else {
            const __half* Ah = (const __half*)Aptr_;
            uint32_t sA = base + buf * 24576;
            uint32_t sB = sA + 16384;
            #pragma unroll
            for (int rnd = 0; rnd < 4; ++rnd) {
                int idx = rnd * 256 + tid;
                int row = idx >> 3, kb = idx & 7;
                uint32_t off = (uint32_t)(row * 128 + kb * 16);
                cp16(sA + SWZ(off), Ah + (size_t)row * lda + k0 + kb * 8);
            }
            #pragma unroll
            for (int rnd = 0; rnd < 2; ++rnd) {
                int idx = rnd * 256 + tid;
                int n = idx >> 3, kb = idx & 7;
                uint32_t off = (uint32_t)(n * 128 + kb * 16);
                cp16(sB + SWZ(off), Bptr + (size_t)n * ldb + k0 + kb * 8);
            }
            cp_commit();
        }
    };

    load_chunk(0, 0);

    for (int c = 0; c < kChunks; ++c) {
        const int buf = c & 1;
        const bool more = (c + 1 < kChunks);
        if (more) load_chunk(c + 1, buf ^ 1);
        if (!A32) { if (more) cp_wait<1>(); else cp_wait<0>(); }
        __syncthreads();

        const uint32_t Ab = base + buf * 24576;
        const uint32_t Bb = Ab + 16384;
        #pragma unroll
        for (int kk = 0; kk < 4; ++kk) {
            uint32_t ra[2][4], rb[2][4];
            #pragma unroll
            for (int mi = 0; mi < 2; ++mi) {
                int m = wm * 32 + mi * 16 + (lane & 7) + ((lane >> 3) & 1) * 8;
                int kbyte = kk * 32 + ((lane >> 4) & 1) * 16;
                uint32_t off = (uint32_t)(m * 128 + kbyte);
                ldsm4(ra[mi], Ab + SWZ(off));
            }
            #pragma unroll
            for (int p = 0; p < 2; ++p) {
                int n = wn * 32 + p * 16 + (lane & 7) + ((lane >> 4) & 1) * 8;
                int kbyte = kk * 32 + ((lane >> 3) & 1) * 16;
                uint32_t off = (uint32_t)(n * 128 + kbyte);
                ldsm4(rb[p], Bb + SWZ(off));
            }
            #pragma unroll
            for (int mi = 0; mi < 2; ++mi)
                #pragma unroll
                for (int nf = 0; nf < 4; ++nf)
                    mma16816(acc[mi][nf], ra[mi], rb[nf >> 1] + (nf & 1) * 2);
        }
        __syncthreads();
    }
}

// scatter accum into gstage[128][65] (padded fp32 staging in smem)
__device__ __forceinline__ void store_acc(float* gstage, float acc[2][4][4], int tid) {
    const int lane = tid & 31, wid = tid >> 5;
    const int wm = wid & 3, wn = wid >> 2;
    #pragma unroll
    for (int mi = 0; mi < 2; ++mi)
        #pragma unroll
        for (int nf = 0; nf < 4; ++nf) {
            int m = wm * 32 + mi * 16 + (lane >> 2);
            int n = wn * 32 + nf * 8 + 2 * (lane & 3);
            gstage[m * 65 + n]           = acc[mi][nf][0];
            gstage[m * 65 + n + 1]       = acc[mi][nf][1];
            gstage[(m + 8) * 65 + n]     = acc[mi][nf][2];
            gstage[(m + 8) * 65 + n + 1] = acc[mi][nf][3];
        }
}

// ===================== prep kernels ==========================
__global__ void k_convert_wfc(const float* __restrict__ Wfc) {
    int i = blockIdx.x * 256 + threadIdx.x;          // 1M elems
    int n = i >> 10, k = i & 1023;
    g_WfcT16[i] = __float2half(Wfc[(size_t)k * 1024 + n]);
    g_Wfc16[i]  = __float2half(Wfc[i]);
}

__global__ void k_convert_whh(const float* __restrict__ Whh) {
    int i = blockIdx.x * 256 + threadIdx.x;          // 4M elems
    int np = i >> 10, j = i & 1023;
    int r = (np & 3) * 1024 + (np >> 2);             // orig gate row
    g_Wcat[(size_t)np * 2048 + 1024 + j] = __float2half(Whh[(size_t)r * 1024 + j]);
}

__global__ void k_bias(const float* __restrict__ Wih, const float* __restrict__ bih,
                       const float* __restrict__ bhh, const float* __restrict__ bfc) {
    int w = (blockIdx.x * blockDim.x + threadIdx.x) >> 5;   // n' row, 0..4095
    int lane = threadIdx.x & 31;
    if (w >= 4096) return;
    int r = (w & 3) * 1024 + (w >> 2);
    float s = 0.f;
    for (int j = lane; j < 1024; j += 32) s += Wih[(size_t)r * 1024 + j] * bfc[j];
    #pragma unroll
    for (int o = 16; o; o >>= 1) s += __shfl_down_sync(0xffffffffu, s, o);
    if (lane == 0) {
        float b0 = bih[r] + bhh[r];
        g_bias0[w] = b0;
        g_biasA[w] = b0 + s;
    }
}

__global__ void k_init(const float* __restrict__ cvec) {
    int i = blockIdx.x * 256 + threadIdx.x;          // 256K elems
    if (i == 0) g_bar = 0u;                          // reset grid barrier each launch
    int b = i >> 10, u = i & 1023;
    float cv = cvec[i];
    g_X16[0][(size_t)b * 2048 + u] = __float2half(0.f);          // i_0 = 0 fold
    g_X16[0][(size_t)b * 2048 + 1024 + u] = __float2half(cv);    // h_0 = c_vector
}

// Wcomb = W_ih @ W_fc, fp16 into g_Wcat left half with row perm n'=4u+g.
__global__ __launch_bounds__(256, 1) void k_prep(const float* __restrict__ Wih) {
    extern __shared__ char smem[];
    const int mt = blockIdx.x, nt = blockIdx.y;      // 32 x 16
    float acc[2][4][4];
    gemm_core<true>(Wih + (size_t)mt * 128 * 1024, 1024,
                    g_WfcT16 + (size_t)nt * 64 * 1024, 1024, 16, smem, acc);
    float* gstage = (float*)smem;
    store_acc(gstage, acc, threadIdx.x);
    __syncthreads();
    #pragma unroll
    for (int i = 0; i < 32; ++i) {                   // 8192 elems
        int idx = i * 256 + threadIdx.x;
        int rl = idx >> 6, col = idx & 63;
        int r = mt * 128 + rl;
        int np = 4 * (r & 1023) + (r >> 10);
        g_Wcat[(size_t)np * 2048 + nt * 64 + col] = __float2half(gstage[rl * 65 + col]);
    }
}

// ===================== persistent step kernel ================
// ONE kernel runs all 256 steps. grid = 128 CTAs (1/SM, all co-resident):
// blockIdx.x = mt + 2*nt; mt in {0,1} batch tile, nt in [0,64) unit tile.
// Cell state lives in registers. Device-wide spin barrier between steps.
// smem: [0, 98304) = 2 stages x (A 32KB + B 16KB), K-chunk 128 as 2x64 subs;
//       [98304, +512) = bias slice (bias0 | biasA).
__global__ __launch_bounds__(256, 1) void k_steps(const float* __restrict__ cvec,
                                                  float* __restrict__ hout,
                                                  float* __restrict__ cout) {
    extern __shared__ char smem[];
    const int tid = threadIdx.x;
    const int lane = tid & 31, wid = tid >> 5;
    const int wm = wid & 3, wn = wid >> 2;
    const int mt = blockIdx.x & 1, nt = blockIdx.x >> 1;
    const uint32_t base = smem_u32_of(smem);
    float* sbias = (float*)(smem + 98304);

    if (tid < 64) {
        sbias[tid]      = g_bias0[nt * 64 + tid];
        sbias[64 + tid] = g_biasA[nt * 64 + tid];
    }
    // fp32 cell state in registers: cell i -> (row = (i*256+tid)>>4, ul = &15)
    float creg[8];
    #pragma unroll
    for (int i = 0; i < 8; ++i) {
        int idx = i * 256 + tid;
        int bg = mt * 128 + (idx >> 4), ug = nt * 16 + (idx & 15);
        creg[i] = cvec[(size_t)bg * 1024 + ug];
    }
    __syncthreads();

    const __half* Bp = g_Wcat + (size_t)nt * 64 * 2048;

    for (int t = 0; t < SEQLEN; ++t) {
        const __half* Xsrc = g_X16[t & 1] + (size_t)mt * 128 * 2048;
        __half* Xdst = g_X16[(t & 1) ^ 1];

        float acc[2][4][4];
        #pragma unroll
        for (int mi = 0; mi < 2; ++mi)
            #pragma unroll
            for (int nf = 0; nf < 4; ++nf)
                #pragma unroll
                for (int e = 0; e < 4; ++e) acc[mi][nf][e] = 0.f;

        auto load_chunk = [&](int c, int stg) {
            const int k0 = c * 128;
            uint32_t sA = base + stg * 49152;
            uint32_t sB = sA + 32768;
            #pragma unroll
            for (int sub = 0; sub < 2; ++sub) {
                #pragma unroll
                for (int rnd = 0; rnd < 4; ++rnd) {
                    int idx = rnd * 256 + tid;
                    int row = idx >> 3, kb = idx & 7;
                    uint32_t off = (uint32_t)(row * 128 + kb * 16);
                    cp16(sA + sub * 16384 + SWZ(off),
                         Xsrc + (size_t)row * 2048 + k0 + sub * 64 + kb * 8);
                }
                #pragma unroll
                for (int rnd = 0; rnd < 2; ++rnd) {
                    int idx = rnd * 256 + tid;
                    int n = idx >> 3, kb = idx & 7;
                    uint32_t off = (uint32_t)(n * 128 + kb * 16);
                    cp16(sB + sub * 8192 + SWZ(off),
                         Bp + (size_t)n * 2048 + k0 + sub * 64 + kb * 8);
                }
            }
            cp_commit();
        };

        load_chunk(0, 0);
        for (int c = 0; c < 16; ++c) {
            const int stg = c & 1;
            const bool more = (c + 1 < 16);
            if (more) load_chunk(c + 1, stg ^ 1);
            if (more) cp_wait<1>(); else cp_wait<0>();
            __syncthreads();

            const uint32_t Ab = base + stg * 49152;
            const uint32_t Bb = Ab + 32768;
            #pragma unroll
            for (int sub = 0; sub < 2; ++sub) {
                const uint32_t As = Ab + sub * 16384;
                const uint32_t Bs = Bb + sub * 8192;
                #pragma unroll
                for (int kk = 0; kk < 4; ++kk) {
                    uint32_t ra[2][4], rb[2][4];
                    #pragma unroll
                    for (int mi = 0; mi < 2; ++mi) {
                        int m = wm * 32 + mi * 16 + (lane & 7) + ((lane >> 3) & 1) * 8;
                        int kbyte = kk * 32 + ((lane >> 4) & 1) * 16;
                        uint32_t off = (uint32_t)(m * 128 + kbyte);
                        ldsm4(ra[mi], As + SWZ(off));
                    }
                    #pragma unroll
                    for (int p = 0; p < 2; ++p) {
                        int n = wn * 32 + p * 16 + (lane & 7) + ((lane >> 4) & 1) * 8;
                        int kbyte = kk * 32 + ((lane >> 3) & 1) * 16;
                        uint32_t off = (uint32_t)(n * 128 + kbyte);
                        ldsm4(rb[p], Bs + SWZ(off));
                    }
                    #pragma unroll
                    for (int mi = 0; mi < 2; ++mi)
                        #pragma unroll
                        for (int nf = 0; nf < 4; ++nf)
                            mma16816(acc[mi][nf], ra[mi], rb[nf >> 1] + (nf & 1) * 2);
                }
            }
            __syncthreads();
        }

        // fused cell epilogue
        float* gstage = (float*)smem;
        store_acc(gstage, acc, tid);
        __syncthreads();
        const float* sb = (t == 0) ? sbias : (sbias + 64);
        #pragma unroll
        for (int i = 0; i < 8; ++i) {
            int idx = i * 256 + tid;
            int row = idx >> 4, ul = idx & 15;
            int ug = nt * 16 + ul, bg = mt * 128 + row;
            float ip = gstage[row * 65 + 4 * ul + 0] + sb[4 * ul + 0];
            float fp = gstage[row * 65 + 4 * ul + 1] + sb[4 * ul + 1];
            float gp = gstage[row * 65 + 4 * ul + 2] + sb[4 * ul + 2];
            float op = gstage[row * 65 + 4 * ul + 3] + sb[4 * ul + 3];
            float cn = sigf(fp) * creg[i] + sigf(ip) * tanhf(gp);
            float hn = sigf(op) * tanhf(cn);
            creg[i] = cn;
            Xdst[(size_t)bg * 2048 + ug] = __float2half(cn);
            Xdst[(size_t)bg * 2048 + 1024 + ug] = __float2half(hn);
            size_t o = (size_t)bg * (SEQLEN * 1024) + (size_t)t * 1024 + ug;
            hout[o] = hn;
            cout[o] = cn;
        }

        // device-wide barrier (release: fence+atomic; acquire: ld.acquire.gpu)
        if (t + 1 < SEQLEN) {
            __syncthreads();
            if (tid == 0) {
                __threadfence();
                atomicAdd(&g_bar, 1u);
                const unsigned target = 128u * (unsigned)(t + 1);
                unsigned v;
                do {
                    asm volatile("ld.acquire.gpu.u32 %0, [%1];" : "=r"(v) : "l"(&g_bar));
                    if (v < target) __nanosleep(64);
                } while (v < target);
            }
            __syncthreads();
        }
    }
}

// ===================== final outputs GEMM ====================
// outputs[m, n] = c_states[m, :] @ W_fc[n, :] + b_fc[n]; M=65536, N=1024, K=1024.
__global__ __launch_bounds__(256, 1) void k_final(const float* __restrict__ Call,
                                                  const float* __restrict__ bfc,
                                                  float* __restrict__ outp) {
    extern __shared__ char smem[];
    const int nt = blockIdx.x, mt = blockIdx.y;      // 16 x 512 (nt fast for A reuse)
    float acc[2][4][4];
    gemm_core<true>(Call + (size_t)mt * 128 * 1024, 1024,
                    g_Wfc16 + (size_t)nt * 64 * 1024, 1024, 16, smem, acc);
    float* gstage = (float*)smem;
    store_acc(gstage, acc, threadIdx.x);
    __syncthreads();
    #pragma unroll
    for (int i = 0; i < 32; ++i) {
        int idx = i * 256 + threadIdx.x;
        int rl = idx >> 6, col = idx & 63;
        outp[(size_t)(mt * 128 + rl) * 1024 + nt * 64 + col] =
            gstage[rl * 65 + col] + bfc[nt * 64 + col];
    }
}

// ===================== host launcher =========================
extern "C" void kernel_launch(void* const* d_in, const int* in_sizes, int n_in,
                              void* d_out, int out_size) {
    const float* c_vec = (const float*)d_in[0];
    const float* W_ih  = (const float*)d_in[1];
    const float* W_hh  = (const float*)d_in[2];
    const float* b_ih  = (const float*)d_in[3];
    const float* b_hh  = (const float*)d_in[4];
    const float* W_fc  = (const float*)d_in[5];
    const float* b_fc  = (const float*)d_in[6];
    float* out = (float*)d_out;
    const size_t HSZ = (size_t)NBATCH * SEQLEN * 1024;
    float* hout = out;
    float* cout = out + HSZ;
    float* oout = out + 2 * HSZ;

    cudaFuncSetAttribute(k_prep,  cudaFuncAttributeMaxDynamicSharedMemorySize, 49152);
    cudaFuncSetAttribute(k_steps, cudaFuncAttributeMaxDynamicSharedMemorySize, 98816);
    cudaFuncSetAttribute(k_final, cudaFuncAttributeMaxDynamicSharedMemorySize, 49152);

    k_convert_wfc<<<4096, 256>>>(W_fc);
    k_convert_whh<<<16384, 256>>>(W_hh);
    k_bias<<<512, 256>>>(W_ih, b_ih, b_hh, b_fc);
    k_init<<<1024, 256>>>(c_vec);

    dim3 gp(32, 16);
    k_prep<<<gp, 256, 49152>>>(W_ih);

    k_steps<<<128, 256, 98816>>>(c_vec, hout, cout);

    dim3 gf(16, 512);
    k_final<<<gf, 256, 49152>>>(cout, b_fc, oout);
}

// round 13
// speedup vs baseline: 1.1137x; 1.0114x over previous
#include <cuda_runtime.h>
#include <cuda_fp16.h>
#include <cstdint>
#include <cstddef>

// ===================== problem constants =====================
#define SEQLEN 256
#define NBATCH 256
// hidden = 1024, gates = 4096, concat K = 2048

// ===================== device scratch ========================
static __device__ __half g_Wcat[(size_t)4096 * 2048];     // [Wcomb | Whh], rows n'=4u+g
static __device__ __half g_WfcT16[(size_t)1024 * 1024];   // W_fc^T fp16 (prep GEMM B)
static __device__ __half g_Wfc16[(size_t)1024 * 1024];    // W_fc fp16 (final GEMM B)
static __device__ float  g_bias0[4096];                   // perm(b_ih+b_hh)
static __device__ float  g_biasA[4096];                   // bias0 + perm(W_ih@b_fc)
static __device__ __half g_X16[2][(size_t)NBATCH * 2048]; // per row: [c16 | h16]
static __device__ unsigned g_bar;                         // grid barrier counter

// ===================== helpers ===============================
__device__ __forceinline__ uint32_t smem_u32_of(const void* p) {
    uint32_t a;
    asm("{ .reg .u64 t; cvta.to.shared.u64 t, %1; cvt.u32.u64 %0, t; }" : "=r"(a) : "l"(p));
    return a;
}
__device__ __forceinline__ uint32_t f22u(float a, float b) {
    __half2 h = __floats2half2_rn(a, b);
    return *reinterpret_cast<uint32_t*>(&h);
}
__device__ __forceinline__ float sigf(float x) { return 1.f / (1.f + __expf(-x)); }

__device__ __forceinline__ void ldsm4(uint32_t* r, uint32_t addr) {
    asm volatile("ldmatrix.sync.aligned.m8n8.x4.shared.b16 {%0,%1,%2,%3}, [%4];"
                 : "=r"(r[0]), "=r"(r[1]), "=r"(r[2]), "=r"(r[3]) : "r"(addr));
}
__device__ __forceinline__ void mma16816(float* d, const uint32_t* a, const uint32_t* b) {
    asm volatile("mma.sync.aligned.m16n8k16.row.col.f32.f16.f16.f32 "
                 "{%0,%1,%2,%3}, {%4,%5,%6,%7}, {%8,%9}, {%0,%1,%2,%3};"
                 : "+f"(d[0]), "+f"(d[1]), "+f"(d[2]), "+f"(d[3])
                 : "r"(a[0]), "r"(a[1]), "r"(a[2]), "r"(a[3]), "r"(b[0]), "r"(b[1]));
}
__device__ __forceinline__ void cp16(uint32_t saddr, const void* g) {
    asm volatile("cp.async.cg.shared.global [%0], [%1], 16;" :: "r"(saddr), "l"(g));
}
__device__ __forceinline__ void cp_commit() { asm volatile("cp.async.commit_group;" ::: "memory"); }
template <int N> __device__ __forceinline__ void cp_wait() {
    asm volatile("cp.async.wait_group %0;" :: "n"(N) : "memory");
}
#define SWZ(off) ((off) ^ (((off) >> 3) & 0x70))

// ===================== GEMM core (launch-per-tile path) ======
// acc[2][4][4] (fp32) = A[128, K] @ B[64, K]^T on a 128x64 CTA tile.
// 8 warps as 4(M) x 2(N), warp tile 32x32, mma.sync m16n8k16.
// K consumed in 64-wide chunks, double-buffered smem (A 16KB + B 8KB per buf).
template <bool A32>
__device__ __forceinline__ void gemm_core(
    const void* Aptr_, int lda, const __half* Bptr, int ldb,
    int kChunks, char* smem, float acc[2][4][4])
{
    const int tid = threadIdx.x;
    const int lane = tid & 31, wid = tid >> 5;
    const int wm = wid & 3, wn = wid >> 2;
    const uint32_t base = smem_u32_of(smem);

    #pragma unroll
    for (int mi = 0; mi < 2; ++mi)
        #pragma unroll
        for (int nf = 0; nf < 4; ++nf)
            #pragma unroll
            for (int e = 0; e < 4; ++e) acc[mi][nf][e] = 0.f;

    auto load_chunk = [&](int c, int buf) {
        const int k0 = c * 64;
        char* dA = smem + buf * 24576;
        char* dB = dA + 16384;
        if (A32) {
            const float* Af = (const float*)Aptr_;
            #pragma unroll
            for (int rnd = 0; rnd < 4; ++rnd) {
                int idx = rnd * 256 + tid;
                int row = idx >> 3, kb = idx & 7;
                const float* g = Af + (size_t)row * lda + k0 + kb * 8;
                float4 f0 = *(const float4*)g;
                float4 f1 = *(const float4*)(g + 4);
                uint4 v = make_uint4(f22u(f0.x, f0.y), f22u(f0.z, f0.w),
                                     f22u(f1.x, f1.y), f22u(f1.z, f1.w));
                uint32_t off = (uint32_t)(row * 128 + kb * 16);
                *(uint4*)(dA + SWZ(off)) = v;
            }
            #pragma unroll
            for (int rnd = 0; rnd < 2; ++rnd) {
                int idx = rnd * 256 + tid;
                int n = idx >> 3, kb = idx & 7;
                uint4 v = *(const uint4*)(Bptr + (size_t)n * ldb + k0 + kb * 8);
                uint32_t off = (uint32_t)(n * 128 + kb * 16);
                *(uint4*)(dB + SWZ(off)) = v;
            }
        } else {
            const __half* Ah = (const __half*)Aptr_;
            uint32_t sA = base + buf * 24576;
            uint32_t sB = sA + 16384;
            #pragma unroll
            for (int rnd = 0; rnd < 4; ++rnd) {
                int idx = rnd * 256 + tid;
                int row = idx >> 3, kb = idx & 7;
                uint32_t off = (uint32_t)(row * 128 + kb * 16);
                cp16(sA + SWZ(off), Ah + (size_t)row * lda + k0 + kb * 8);
            }
            #pragma unroll
            for (int rnd = 0; rnd < 2; ++rnd) {
                int idx = rnd * 256 + tid;
                int n = idx >> 3, kb = idx & 7;
                uint32_t off = (uint32_t)(n * 128 + kb * 16);
                cp16(sB + SWZ(off), Bptr + (size_t)n * ldb + k0 + kb * 8);
            }
            cp_commit();
        }
    };

    load_chunk(0, 0);

    for (int c = 0; c < kChunks; ++c) {
        const int buf = c & 1;
        const bool more = (c + 1 < kChunks);
        if (more) load_chunk(c + 1, buf ^ 1);
        if (!A32) { if (more) cp_wait<1>(); else cp_wait<0>(); }
        __syncthreads();

        const uint32_t Ab = base + buf * 24576;
        const uint32_t Bb = Ab + 16384;
        #pragma unroll
        for (int kk = 0; kk < 4; ++kk) {
            uint32_t ra[2][4], rb[2][4];
            #pragma unroll
            for (int mi = 0; mi < 2; ++mi) {
                int m = wm * 32 + mi * 16 + (lane & 7) + ((lane >> 3) & 1) * 8;
                int kbyte = kk * 32 + ((lane >> 4) & 1) * 16;
                uint32_t off = (uint32_t)(m * 128 + kbyte);
                ldsm4(ra[mi], Ab + SWZ(off));
            }
            #pragma unroll
            for (int p = 0; p < 2; ++p) {
                int n = wn * 32 + p * 16 + (lane & 7) + ((lane >> 4) & 1) * 8;
                int kbyte = kk * 32 + ((lane >> 3) & 1) * 16;
                uint32_t off = (uint32_t)(n * 128 + kbyte);
                ldsm4(rb[p], Bb + SWZ(off));
            }
            #pragma unroll
            for (int mi = 0; mi < 2; ++mi)
                #pragma unroll
                for (int nf = 0; nf < 4; ++nf)
                    mma16816(acc[mi][nf], ra[mi], rb[nf >> 1] + (nf & 1) * 2);
        }
        __syncthreads();
    }
}

// scatter accum into gstage[128][65] (padded fp32 staging in smem)
__device__ __forceinline__ void store_acc(float* gstage, float acc[2][4][4], int tid) {
    const int lane = tid & 31, wid = tid >> 5;
    const int wm = wid & 3, wn = wid >> 2;
    #pragma unroll
    for (int mi = 0; mi < 2; ++mi)
        #pragma unroll
        for (int nf = 0; nf < 4; ++nf) {
            int m = wm * 32 + mi * 16 + (lane >> 2);
            int n = wn * 32 + nf * 8 + 2 * (lane & 3);
            gstage[m * 65 + n]           = acc[mi][nf][0];
            gstage[m * 65 + n + 1]       = acc[mi][nf][1];
            gstage[(m + 8) * 65 + n]     = acc[mi][nf][2];
            gstage[(m + 8) * 65 + n + 1] = acc[mi][nf][3];
        }
}

// ===================== prep kernels ==========================
__global__ void k_convert_wfc(const float* __restrict__ Wfc) {
    int i = blockIdx.x * 256 + threadIdx.x;          // 1M elems
    int n = i >> 10, k = i & 1023;
    g_WfcT16[i] = __float2half(Wfc[(size_t)k * 1024 + n]);
    g_Wfc16[i]  = __float2half(Wfc[i]);
}

__global__ void k_convert_whh(const float* __restrict__ Whh) {
    int i = blockIdx.x * 256 + threadIdx.x;          // 4M elems
    int np = i >> 10, j = i & 1023;
    int r = (np & 3) * 1024 + (np >> 2);             // orig gate row
    g_Wcat[(size_t)np * 2048 + 1024 + j] = __float2half(Whh[(size_t)r * 1024 + j]);
}

__global__ void k_bias(const float* __restrict__ Wih, const float* __restrict__ bih,
                       const float* __restrict__ bhh, const float* __restrict__ bfc) {
    int w = (blockIdx.x * blockDim.x + threadIdx.x) >> 5;   // n' row, 0..4095
    int lane = threadIdx.x & 31;
    if (w >= 4096) return;
    int r = (w & 3) * 1024 + (w >> 2);
    float s = 0.f;
    for (int j = lane; j < 1024; j += 32) s += Wih[(size_t)r * 1024 + j] * bfc[j];
    #pragma unroll
    for (int o = 16; o; o >>= 1) s += __shfl_down_sync(0xffffffffu, s, o);
    if (lane == 0) {
        float b0 = bih[r] + bhh[r];
        g_bias0[w] = b0;
        g_biasA[w] = b0 + s;
    }
}

__global__ void k_init(const float* __restrict__ cvec) {
    int i = blockIdx.x * 256 + threadIdx.x;          // 256K elems
    if (i == 0) g_bar = 0u;                          // reset grid barrier each launch
    int b = i >> 10, u = i & 1023;
    float cv = cvec[i];
    g_X16[0][(size_t)b * 2048 + u] = __float2half(0.f);          // i_0 = 0 fold
    g_X16[0][(size_t)b * 2048 + 1024 + u] = __float2half(cv);    // h_0 = c_vector
}

// Wcomb = W_ih @ W_fc, fp16 into g_Wcat left half with row perm n'=4u+g.
__global__ __launch_bounds__(256, 1) void k_prep(const float* __restrict__ Wih) {
    extern __shared__ char smem[];
    const int mt = blockIdx.x, nt = blockIdx.y;      // 32 x 16
    float acc[2][4][4];
    gemm_core<true>(Wih + (size_t)mt * 128 * 1024, 1024,
                    g_WfcT16 + (size_t)nt * 64 * 1024, 1024, 16, smem, acc);
    float* gstage = (float*)smem;
    store_acc(gstage, acc, threadIdx.x);
    __syncthreads();
    #pragma unroll
    for (int i = 0; i < 32; ++i) {                   // 8192 elems
        int idx = i * 256 + threadIdx.x;
        int rl = idx >> 6, col = idx & 63;
        int r = mt * 128 + rl;
        int np = 4 * (r & 1023) + (r >> 10);
        g_Wcat[(size_t)np * 2048 + nt * 64 + col] = __float2half(gstage[rl * 65 + col]);
    }
}

// ===================== persistent step kernel ================
// ONE kernel runs all 256 steps. grid = 128 CTAs (1/SM, co-resident):
// blockIdx.x = mt + 2*nt; mt in {0,1} batch tile, nt in [0,64) unit tile.
// Cell state in registers. Device-wide spin barrier between steps.
// smem: 4 stages x 24576 B (A 16KB + B 8KB, K-chunk 64) = 98304;
//       [98304, +512) bias slice. Epilogue staging overlays stages 2-3.
// Pipeline: depth-3 prefetch, ONE __syncthreads per chunk (overwrite target
// is 2 iterations stale). Static B chunks 0,1 prefetched ACROSS the grid
// barrier (no inter-CTA dependency).
__global__ __launch_bounds__(256, 1) void k_steps(const float* __restrict__ cvec,
                                                  float* __restrict__ hout,
                                                  float* __restrict__ cout) {
    extern __shared__ char smem[];
    const int tid = threadIdx.x;
    const int lane = tid & 31, wid = tid >> 5;
    const int wm = wid & 3, wn = wid >> 2;
    const int mt = blockIdx.x & 1, nt = blockIdx.x >> 1;
    const uint32_t base = smem_u32_of(smem);
    float* sbias = (float*)(smem + 98304);

    if (tid < 64) {
        sbias[tid]      = g_bias0[nt * 64 + tid];
        sbias[64 + tid] = g_biasA[nt * 64 + tid];
    }
    // fp32 cell state in registers: cell i -> (row = (i*256+tid)>>4, ul = &15)
    float creg[8];
    #pragma unroll
    for (int i = 0; i < 8; ++i) {
        int idx = i * 256 + tid;
        int bg = mt * 128 + (idx >> 4), ug = nt * 16 + (idx & 15);
        creg[i] = cvec[(size_t)bg * 1024 + ug];
    }
    __syncthreads();

    const __half* Bp = g_Wcat + (size_t)nt * 64 * 2048;

    auto loadB = [&](int c, int stg) {               // 2 cp16/thread, 8KB
        const int k0 = c * 64;
        uint32_t sB = base + stg * 24576 + 16384;
        #pragma unroll
        for (int rnd = 0; rnd < 2; ++rnd) {
            int idx = rnd * 256 + tid;
            int n = idx >> 3, kb = idx & 7;
            uint32_t off = (uint32_t)(n * 128 + kb * 16);
            cp16(sB + SWZ(off), Bp + (size_t)n * 2048 + k0 + kb * 8);
        }
    };
    auto loadA = [&](const __half* Xsrc, int c, int stg) {   // 4 cp16/thread, 16KB
        const int k0 = c * 64;
        uint32_t sA = base + stg * 24576;
        #pragma unroll
        for (int rnd = 0; rnd < 4; ++rnd) {
            int idx = rnd * 256 + tid;
            int row = idx >> 3, kb = idx & 7;
            uint32_t off = (uint32_t)(row * 128 + kb * 16);
            cp16(sA + SWZ(off), Xsrc + (size_t)row * 2048 + k0 + kb * 8);
        }
    };

    // initial static-B prefetch for step 0 (stages 0,1)
    loadB(0, 0); loadB(1, 1); cp_commit();

    for (int t = 0; t < SEQLEN; ++t) {
        const __half* Xsrc = g_X16[t & 1] + (size_t)mt * 128 * 2048;
        __half* Xdst = g_X16[(t & 1) ^ 1];

        float acc[2][4][4];
        #pragma unroll
        for (int mi = 0; mi < 2; ++mi)
            #pragma unroll
            for (int nf = 0; nf < 4; ++nf)
                #pragma unroll
                for (int e = 0; e < 4; ++e) acc[mi][nf][e] = 0.f;

        loadA(Xsrc, 0, 0); cp_commit();
        loadA(Xsrc, 1, 1); cp_commit();

        for (int c = 0; c < 32; ++c) {
            if (c + 2 < 32) {
                loadA(Xsrc, c + 2, (c + 2) & 3);
                loadB(c + 2, (c + 2) & 3);
                cp_commit();
                cp_wait<2>();
            } else if (c == 30) {
                cp_wait<1>();
            } else {
                cp_wait<0>();
            }
            __syncthreads();

            const uint32_t As = base + (uint32_t)(c & 3) * 24576;
            const uint32_t Bs = As + 16384;
            #pragma unroll
            for (int kk = 0; kk < 4; ++kk) {
                uint32_t ra[2][4], rb[2][4];
                #pragma unroll
                for (int mi = 0; mi < 2; ++mi) {
                    int m = wm * 32 + mi * 16 + (lane & 7) + ((lane >> 3) & 1) * 8;
                    int kbyte = kk * 32 + ((lane >> 4) & 1) * 16;
                    uint32_t off = (uint32_t)(m * 128 + kbyte);
                    ldsm4(ra[mi], As + SWZ(off));
                }
                #pragma unroll
                for (int p = 0; p < 2; ++p) {
                    int n = wn * 32 + p * 16 + (lane & 7) + ((lane >> 4) & 1) * 8;
                    int kbyte = kk * 32 + ((lane >> 3) & 1) * 16;
                    uint32_t off = (uint32_t)(n * 128 + kbyte);
                    ldsm4(rb[p], Bs + SWZ(off));
                }
                #pragma unroll
                for (int mi = 0; mi < 2; ++mi)
                    #pragma unroll
                    for (int nf = 0; nf < 4; ++nf)
                        mma16816(acc[mi][nf], ra[mi], rb[nf >> 1] + (nf & 1) * 2);
            }
        }

        // fused cell epilogue (staging overlays stages 2-3; disjoint from
        // the pre-barrier B prefetch targets in stages 0-1)
        __syncthreads();
        float* gstage = (float*)(smem + 49152);
        store_acc(gstage, acc, tid);
        __syncthreads();
        const float* sb = (t == 0) ? sbias : (sbias + 64);
        #pragma unroll
        for (int i = 0; i < 8; ++i) {
            int idx = i * 256 + tid;
            int row = idx >> 4, ul = idx & 15;
            int ug = nt * 16 + ul, bg = mt * 128 + row;
            float ip = gstage[row * 65 + 4 * ul + 0] + sb[4 * ul + 0];
            float fp = gstage[row * 65 + 4 * ul + 1] + sb[4 * ul + 1];
            float gp = gstage[row * 65 + 4 * ul + 2] + sb[4 * ul + 2];
            float op = gstage[row * 65 + 4 * ul + 3] + sb[4 * ul + 3];
            float cn = sigf(fp) * creg[i] + sigf(ip) * tanhf(gp);
            float hn = sigf(op) * tanhf(cn);
            creg[i] = cn;
            Xdst[(size_t)bg * 2048 + ug] = __float2half(cn);
            Xdst[(size_t)bg * 2048 + 1024 + ug] = __float2half(hn);
            size_t o = (size_t)bg * (SEQLEN * 1024) + (size_t)t * 1024 + ug;
            hout[o] = hn;
            cout[o] = cn;
        }

        // device-wide barrier (release: fence+atomic; acquire: ld.acquire.gpu)
        // Static-B prefetch for the next step is issued BEFORE the spin.
        if (t + 1 < SEQLEN) {
            __syncthreads();
            loadB(0, 0); loadB(1, 1); cp_commit();
            if (tid == 0) {
                __threadfence();
                atomicAdd(&g_bar, 1u);
                const unsigned target = 128u * (unsigned)(t + 1);
                unsigned v;
                do {
                    asm volatile("ld.acquire.gpu.u32 %0, [%1];" : "=r"(v) : "l"(&g_bar));
                    if (v < target) __nanosleep(64);
                } while (v < target);
            }
            __syncthreads();
        }
    }
}

// ===================== final outputs GEMM ====================
// outputs[m, n] = c_states[m, :] @ W_fc[n, :] + b_fc[n]; M=65536, N=1024, K=1024.
__global__ __launch_bounds__(256, 1) void k_final(const float* __restrict__ Call,
                                                  const float* __restrict__ bfc,
                                                  float* __restrict__ outp) {
    extern __shared__ char smem[];
    const int nt = blockIdx.x, mt = blockIdx.y;      // 16 x 512 (nt fast for A reuse)
    float acc[2][4][4];
    gemm_core<true>(Call + (size_t)mt * 128 * 1024, 1024,
                    g_Wfc16 + (size_t)nt * 64 * 1024, 1024, 16, smem, acc);
    float* gstage = (float*)smem;
    store_acc(gstage, acc, threadIdx.x);
    __syncthreads();
    #pragma unroll
    for (int i = 0; i < 32; ++i) {
        int idx = i * 256 + threadIdx.x;
        int rl = idx >> 6, col = idx & 63;
        outp[(size_t)(mt * 128 + rl) * 1024 + nt * 64 + col] =
            gstage[rl * 65 + col] + bfc[nt * 64 + col];
    }
}

// ===================== host launcher =========================
extern "C" void kernel_launch(void* const* d_in, const int* in_sizes, int n_in,
                              void* d_out, int out_size) {
    const float* c_vec = (const float*)d_in[0];
    const float* W_ih  = (const float*)d_in[1];
    const float* W_hh  = (const float*)d_in[2];
    const float* b_ih  = (const float*)d_in[3];
    const float* b_hh  = (const float*)d_in[4];
    const float* W_fc  = (const float*)d_in[5];
    const float* b_fc  = (const float*)d_in[6];
    float* out = (float*)d_out;
    const size_t HSZ = (size_t)NBATCH * SEQLEN * 1024;
    float* hout = out;
    float* cout = out + HSZ;
    float* oout = out + 2 * HSZ;

    cudaFuncSetAttribute(k_prep,  cudaFuncAttributeMaxDynamicSharedMemorySize, 49152);
    cudaFuncSetAttribute(k_steps, cudaFuncAttributeMaxDynamicSharedMemorySize, 98816);
    cudaFuncSetAttribute(k_final, cudaFuncAttributeMaxDynamicSharedMemorySize, 49152);

    k_convert_wfc<<<4096, 256>>>(W_fc);
    k_convert_whh<<<16384, 256>>>(W_hh);
    k_bias<<<512, 256>>>(W_ih, b_ih, b_hh, b_fc);
    k_init<<<1024, 256>>>(c_vec);

    dim3 gp(32, 16);
    k_prep<<<gp, 256, 49152>>>(W_ih);

    k_steps<<<128, 256, 98816>>>(c_vec, hout, cout);

    dim3 gf(16, 512);
    k_final<<<gf, 256, 49152>>>(cout, b_fc, oout);
}